// round 2
// baseline (speedup 1.0000x reference)
#include <cuda_runtime.h>
#include <math.h>

// Problem constants
#define NB   16
#define CIN  512
#define COUT 512
#define HH   64
#define WW   64
#define HW   (HH*WW)           // 4096
#define STY  512
#define KT   9                 // 3x3 taps

// Scratch (device globals — allocation-free rule)
__device__ float g_s[NB*CIN];        // modulation scales s[n][ci]
__device__ float g_wsq[COUT*CIN];    // sum_k weight^2 per (co,ci)
__device__ float g_demod[NB*COUT];   // demod[n][co]

// ---------------------------------------------------------------------------
// Kernel 1: s[n,ci] = style[n,:] . style_w[ci,:] + style_b[ci]
// ---------------------------------------------------------------------------
__global__ void k_style(const float* __restrict__ style,
                        const float* __restrict__ style_w,
                        const float* __restrict__ style_b)
{
    int idx = blockIdx.x * blockDim.x + threadIdx.x;   // NB*CIN = 8192
    if (idx >= NB*CIN) return;
    int n  = idx >> 9;
    int ci = idx & 511;
    const float* st = style   + n  * STY;
    const float* sw = style_w + ci * STY;
    float acc = 0.f;
    #pragma unroll 8
    for (int k = 0; k < STY; ++k) acc += st[k] * sw[k];
    g_s[idx] = acc + style_b[ci];
}

// ---------------------------------------------------------------------------
// Kernel 2: wsq[co,ci] = sum over 9 taps of weight^2
// ---------------------------------------------------------------------------
__global__ void k_wsq(const float* __restrict__ weight)
{
    int idx = blockIdx.x * blockDim.x + threadIdx.x;   // COUT*CIN = 262144
    if (idx >= COUT*CIN) return;
    const float* w = weight + (size_t)idx * KT;
    float acc = 0.f;
    #pragma unroll
    for (int k = 0; k < KT; ++k) acc += w[k] * w[k];
    g_wsq[idx] = acc;
}

// ---------------------------------------------------------------------------
// Kernel 3: demod[n,co] = rsqrt( sum_ci s[n,ci]^2 * wsq[co,ci] + eps )
// ---------------------------------------------------------------------------
__global__ void k_demod()
{
    int idx = blockIdx.x * blockDim.x + threadIdx.x;   // NB*COUT = 8192
    if (idx >= NB*COUT) return;
    int n  = idx >> 9;
    int co = idx & 511;
    const float* sp = g_s   + n  * CIN;
    const float* wq = g_wsq + co * CIN;
    float acc = 0.f;
    #pragma unroll 8
    for (int ci = 0; ci < CIN; ++ci) {
        float sv = sp[ci];
        acc += sv * sv * wq[ci];
    }
    g_demod[idx] = rsqrtf(acc + 1e-8f);
}

// ---------------------------------------------------------------------------
// Kernel 4: shared-weight conv with s folded into x load, demod + noise +
// LeakyReLU epilogue.
//
// Block tile: 128 co x 64 pixels (one output row h). 256 threads.
// Thread tile: 8 co x 4 pixels (32 accumulators).
// K loop: ci in chunks of CK=8, all 9 taps.
// ---------------------------------------------------------------------------
#define CK 8

__global__ __launch_bounds__(256) void k_conv(
    const float* __restrict__ x,
    const float* __restrict__ weight,
    const float* __restrict__ noise,
    const float* __restrict__ noise_w,
    float* __restrict__ out)
{
    // xs[ci][r][c]: rows h-1..h+1 (r=0..2), cols -1..64 (c=0..65)
    __shared__ float xs[CK][3][66];
    // ws[ci][tap][co_l], co_l padded to 129 for conflict-free store/load
    __shared__ float ws[CK][KT][129];

    const int n   = blockIdx.z;
    const int co0 = blockIdx.y * 128;
    const int h   = blockIdx.x;
    const int tid = threadIdx.x;
    const int tx  = tid & 15;      // pixel group: cols tx*4 .. tx*4+3
    const int ty  = tid >> 4;      // co group:    co0 + ty*8 .. +7

    float acc[8][4];
    #pragma unroll
    for (int u = 0; u < 8; ++u)
        #pragma unroll
        for (int j = 0; j < 4; ++j) acc[u][j] = 0.f;

    const float* xn = x + (size_t)n * CIN * HW;
    const float* sn = g_s + n * CIN;

    for (int ci0 = 0; ci0 < CIN; ci0 += CK) {
        __syncthreads();

        // ---- stage x (with halo + zero padding), folding in s[n,ci] ----
        for (int i = tid; i < CK*3*66; i += 256) {
            int ci  = i / 198;
            int rem = i - ci * 198;
            int r   = rem / 66;
            int c   = rem - r * 66;
            int hr  = h - 1 + r;
            int col = c - 1;
            float v = 0.f;
            if ((unsigned)hr < (unsigned)HH && (unsigned)col < (unsigned)WW)
                v = xn[(size_t)(ci0 + ci) * HW + hr * WW + col] * sn[ci0 + ci];
            xs[ci][r][c] = v;
        }

        // ---- stage weights: global [co][ci][tap] -> smem [ci][tap][co] ----
        // i enumerates co_l * 72 + (ci*9+tap) so global reads are contiguous
        // runs of 72 floats per co; the 129-pad makes the transposed store
        // conflict-free (stride 129 between consecutive threads).
        for (int i = tid; i < CK*KT*128; i += 256) {
            int co_l = i / 72;
            int j    = i - co_l * 72;          // j = ci*9 + tap
            int ci   = j / 9;
            int tap  = j - ci * 9;
            ws[ci][tap][co_l] =
                weight[((size_t)(co0 + co_l) * CIN + ci0) * KT + j];
        }

        __syncthreads();

        // ---- compute ----
        #pragma unroll
        for (int ci = 0; ci < CK; ++ci) {
            #pragma unroll
            for (int kh = 0; kh < 3; ++kh) {
                #pragma unroll
                for (int kw = 0; kw < 3; ++kw) {
                    float xr[4], wr[8];
                    #pragma unroll
                    for (int j = 0; j < 4; ++j)
                        xr[j] = xs[ci][kh][tx*4 + j + kw];
                    #pragma unroll
                    for (int u = 0; u < 8; ++u)
                        wr[u] = ws[ci][kh*3 + kw][ty*8 + u];
                    #pragma unroll
                    for (int u = 0; u < 8; ++u)
                        #pragma unroll
                        for (int j = 0; j < 4; ++j)
                            acc[u][j] += wr[u] * xr[j];
                }
            }
        }
    }

    // ---- epilogue: demod, noise injection, LeakyReLU(0.2) ----
    const float nw = noise_w[0];
    #pragma unroll
    for (int u = 0; u < 8; ++u) {
        int co  = co0 + ty*8 + u;
        float d = g_demod[n * COUT + co];
        #pragma unroll
        for (int j = 0; j < 4; ++j) {
            int col  = tx*4 + j;
            float nz = noise[(size_t)n * HW + h * WW + col];
            float v  = acc[u][j] * d + nw * nz;
            v = (v >= 0.f) ? v : 0.2f * v;
            out[(((size_t)n * COUT + co) * HH + h) * WW + col] = v;
        }
    }
}

// ---------------------------------------------------------------------------
// Launcher
// Inputs (metadata order): x, style, noise, weight, style_w, style_b, noise_weight
// ---------------------------------------------------------------------------
extern "C" void kernel_launch(void* const* d_in, const int* in_sizes, int n_in,
                              void* d_out, int out_size)
{
    const float* x        = (const float*)d_in[0];
    const float* style    = (const float*)d_in[1];
    const float* noise    = (const float*)d_in[2];
    const float* weight   = (const float*)d_in[3];
    const float* style_w  = (const float*)d_in[4];
    const float* style_b  = (const float*)d_in[5];
    const float* noise_w  = (const float*)d_in[6];
    float* out            = (float*)d_out;

    k_style<<<(NB*CIN + 255)/256, 256>>>(style, style_w, style_b);
    k_wsq<<<(COUT*CIN + 255)/256, 256>>>(weight);
    k_demod<<<(NB*COUT + 255)/256, 256>>>();

    dim3 grid(HH, COUT/128, NB);   // 64 x 4 x 16 = 4096 blocks
    k_conv<<<grid, 256>>>(x, weight, noise, noise_w, out);
}